// round 13
// baseline (speedup 1.0000x reference)
#include <cuda_runtime.h>
#include <cuda_bf16.h>
#include <math.h>
#include <stdint.h>

#define NN   8192
#define DD   200
#define BB   4
#define EE   4096
#define DEG  16
#define HH   128
#define EPSf 1e-8f
#define MAXDEG 64

// ---------------- scratch (device globals; no allocation allowed) ----------------
__device__ float g_y[NN * HH];        // x @ Wg
__device__ float g_Medge[EE * HH];
__device__ float g_gp[NN * HH];
__device__ float g_fused[NN * HH];
__device__ float g_Wg[DD * HH];       // W @ gnn_w
__device__ float g_bg[HH];            // b @ gnn_w + gnn_b
__device__ int   g_dv_cnt[NN];        // degree AND list cursor
__device__ int   g_de_cnt[EE];
__device__ unsigned g_maskbits[EE];
__device__ int   g_node_edges[NN * MAXDEG];
__device__ float g_alpha_part[256];
__device__ float g_alpha;
__device__ float g_att[BB * HH];
__device__ float g_cvec[BB * HH];

// ---------------- init: zero degree counters + alpha partial sums ----------------
__global__ void k_init(const float* __restrict__ x, const float* __restrict__ gw) {
    __shared__ float sm[256];
    int t = threadIdx.x;
    int gi = blockIdx.x * 256 + t;
    if (gi < NN) g_dv_cnt[gi] = 0;
    float s = 0.f;
    for (int i = gi; i < NN * DD; i += 256 * 256)
        s += x[i] * gw[i % DD];
    sm[t] = s; __syncthreads();
    for (int o = 128; o > 0; o >>= 1) { if (t < o) sm[t] += sm[t + o]; __syncthreads(); }
    if (t == 0) g_alpha_part[blockIdx.x] = sm[0];
}

// ---------------- edge pass: slot-parallel dedup + degree + list fill ----------------
// block 0 additionally finalizes alpha
__global__ void __launch_bounds__(256) k_edge_a(const int* __restrict__ en,
                                                const float* __restrict__ gb) {
    if (blockIdx.x == 0) {
        __shared__ float smf[256];
        int t = threadIdx.x;
        smf[t] = g_alpha_part[t]; __syncthreads();
        for (int o = 128; o > 0; o >>= 1) { if (t < o) smf[t] += smf[t + o]; __syncthreads(); }
        if (t == 0) g_alpha = 1.f / (1.f + expf(-(smf[0] / (float)NN + gb[0])));
    }
    const int gt   = blockIdx.x * 256 + threadIdx.x;   // 0 .. EE*DEG-1
    const int lane = threadIdx.x & 31;
    const int half = lane >> 4;
    const int s    = lane & 15;
    const int e    = (gt >> 5) * 2 + half;
    const int nd   = en[e * DEG + s];
    bool first = true;
#pragma unroll
    for (int j = 0; j < 15; j++) {
        int v = __shfl_sync(0xFFFFFFFFu, nd, (half << 4) + j);
        if (j < s && v == nd) first = false;
    }
    unsigned bal = __ballot_sync(0xFFFFFFFFu, first);
    unsigned m = (bal >> (half * 16)) & 0xFFFFu;
    if (s == 0) { g_maskbits[e] = m; g_de_cnt[e] = __popc(m); }
    if (first) {
        int p = atomicAdd(&g_dv_cnt[nd], 1);
        if (p < MAXDEG) g_node_edges[nd * MAXDEG + p] = e;
    }
}

// ---------------- Wg/bg precompute + per-batch consts, smem-staged ----------------
// blocks 0..25: prec (8 rows each) ; blocks 26..29: per-batch constants
#define KC 40
__global__ void __launch_bounds__(256) k_prec_const(
        const float* __restrict__ W, const float* __restrict__ gnn_w,
        const float* __restrict__ gnn_b, const float* __restrict__ bvec,
        const float* __restrict__ text,
        const float* __restrict__ text_w, const float* __restrict__ text_b,
        const float* __restrict__ in_w,   const float* __restrict__ in_b,
        const float* __restrict__ aow,    const float* __restrict__ aob,
        const float* __restrict__ fgw,    const float* __restrict__ fgb) {
    __shared__ float buf[KC][HH];   // staged weight chunk (20 KB)
    __shared__ float auxv[KC];      // staged input-vector chunk
    __shared__ float aux8[8][KC];   // prec: 8 W-rows chunk
    __shared__ float tpv[HH], vvv[HH], atv[HH];
    const int tid = threadIdx.x;

    if (blockIdx.x >= 26) {
        // ===== per-batch constants, chunk-staged =====
        const int b = blockIdx.x - 26;
        const int j = tid & 127;
        const bool act = (tid < HH);
        float s;
        // -- stage 1: tp = text[b] @ text_w + text_b  (K = 200)
        s = act ? text_b[j] : 0.f;
        for (int c0 = 0; c0 < DD; c0 += KC) {
            int len = DD - c0; if (len > KC) len = KC;
            for (int i = tid; i < len * HH; i += 256)
                buf[i >> 7][i & 127] = text_w[(size_t)(c0 + (i >> 7)) * HH + (i & 127)];
            if (tid < len) auxv[tid] = text[b * DD + c0 + tid];
            __syncthreads();
            if (act) for (int k = 0; k < len; k++) s += auxv[k] * buf[k][j];
            __syncthreads();
        }
        if (act) tpv[j] = s;
        __syncthreads();
        // -- stage 2: vv = tp @ in_w[:, 2H:3H] + in_b[2H:]  (K = 128)
        s = act ? in_b[2 * HH + j] : 0.f;
        for (int c0 = 0; c0 < HH; c0 += KC) {
            int len = HH - c0; if (len > KC) len = KC;
            for (int i = tid; i < len * HH; i += 256)
                buf[i >> 7][i & 127] = in_w[(size_t)(c0 + (i >> 7)) * 3 * HH + 2 * HH + (i & 127)];
            __syncthreads();
            if (act) for (int k = 0; k < len; k++) s += tpv[c0 + k] * buf[k][j];
            __syncthreads();
        }
        if (act) vvv[j] = s;
        __syncthreads();
        // -- stage 3: at = vv @ aow + aob  (K = 128)
        s = act ? aob[j] : 0.f;
        for (int c0 = 0; c0 < HH; c0 += KC) {
            int len = HH - c0; if (len > KC) len = KC;
            for (int i = tid; i < len * HH; i += 256)
                buf[i >> 7][i & 127] = aow[(size_t)(c0 + (i >> 7)) * HH + (i & 127)];
            __syncthreads();
            if (act) for (int k = 0; k < len; k++) s += vvv[c0 + k] * buf[k][j];
            __syncthreads();
        }
        if (act) { atv[j] = s; g_att[b * HH + j] = s; }
        __syncthreads();
        // -- stage 4: cvec = at @ fgw[H:2H] + fgb  (K = 128)
        s = act ? fgb[j] : 0.f;
        for (int c0 = 0; c0 < HH; c0 += KC) {
            int len = HH - c0; if (len > KC) len = KC;
            for (int i = tid; i < len * HH; i += 256)
                buf[i >> 7][i & 127] = fgw[(size_t)(HH + c0 + (i >> 7)) * HH + (i & 127)];
            __syncthreads();
            if (act) for (int k = 0; k < len; k++) s += atv[c0 + k] * buf[k][j];
            __syncthreads();
        }
        if (act) g_cvec[b * HH + j] = s;
        return;
    }

    // ===== prec: 8 rows of (W|b) @ gnn_w per block, chunk-staged =====
    const int r0  = blockIdx.x * 8;
    const int col = tid & 127;
    const int hf  = tid >> 7;     // 0/1 -> rows hf*4..hf*4+3
    float s[4] = {0.f, 0.f, 0.f, 0.f};
    for (int c0 = 0; c0 < DD; c0 += KC) {   // 5 exact chunks of 40
        // stage gnn_w chunk [KC][HH]
        for (int i = tid; i < KC * HH; i += 256)
            buf[i >> 7][i & 127] = gnn_w[(size_t)(c0 + (i >> 7)) * HH + (i & 127)];
        // stage 8 rows of W (row DD = bvec, rows > DD = 0)
        for (int i = tid; i < 8 * KC; i += 256) {
            int rr = i / KC, kk = i % KC;
            int row = r0 + rr;
            float v = 0.f;
            if (row < DD)       v = W[(size_t)row * DD + c0 + kk];
            else if (row == DD) v = bvec[c0 + kk];
            aux8[rr][kk] = v;
        }
        __syncthreads();
#pragma unroll 8
        for (int kk = 0; kk < KC; kk++) {
            float w = buf[kk][col];
#pragma unroll
            for (int i = 0; i < 4; i++) s[i] += aux8[hf * 4 + i][kk] * w;
        }
        __syncthreads();
    }
#pragma unroll
    for (int i = 0; i < 4; i++) {
        int row = r0 + hf * 4 + i;
        if (row < DD)       g_Wg[row * HH + col] = s[i];
        else if (row == DD) g_bg[col] = s[i] + gnn_b[col];
    }
}

// sort each node's edge list for deterministic FP order
__global__ void k_sort() {
    int n = blockIdx.x * blockDim.x + threadIdx.x;
    if (n >= NN) return;
    int len = g_dv_cnt[n]; if (len > MAXDEG) len = MAXDEG;
    int* a = &g_node_edges[n * MAXDEG];
    for (int i = 1; i < len; i++) {
        int key = a[i]; int j = i - 1;
        while (j >= 0 && a[j] > key) { a[j + 1] = a[j]; j--; }
        a[j + 1] = key;
    }
}

// Medge[e,:] over y (128 cols); 4 edges/block, 32 lanes/edge
__global__ void __launch_bounds__(128) k_edge_b(const int* __restrict__ en) {
    __shared__ int   sn[4][DEG];
    __shared__ float sw[4][DEG];
    const int tid = threadIdx.x;
    const int sub = tid >> 5, lane = tid & 31;
    const int e0 = blockIdx.x * 4;
    if (tid < 64) {
        int ee = tid >> 4, s = tid & 15;
        int e = e0 + ee;
        int n = en[e * DEG + s];
        sn[ee][s] = n;
        sw[ee][s] = ((g_maskbits[e] >> s) & 1u)
                      ? rsqrtf((float)g_dv_cnt[n] * (1.f / DEG) + EPSf) : 0.f;
    }
    __syncthreads();
    const int e = e0 + sub;
    float4 acc = make_float4(0.f, 0.f, 0.f, 0.f);
#pragma unroll
    for (int s = 0; s < DEG; s++) {
        float w = sw[sub][s];
        float4 v = ((const float4*)&g_y[(size_t)sn[sub][s] * HH])[lane];
        acc.x += w * v.x; acc.y += w * v.y; acc.z += w * v.z; acc.w += w * v.w;
    }
    float sc = 1.f / ((float)g_de_cnt[e] * (1.f / DEG) + EPSf) * (1.f / (DEG * DEG));
    ((float4*)&g_Medge[(size_t)e * HH])[lane] =
        make_float4(acc.x * sc, acc.y * sc, acc.z * sc, acc.w * sc);
}

// gp = alpha*y + (1-alpha)*dv*sum Medge + bg ; 8 nodes/block (warp per node)
__global__ void __launch_bounds__(256) k_gather() {
    const int n = blockIdx.x * 8 + (threadIdx.x >> 5);
    const int lane = threadIdx.x & 31;
    int len  = g_dv_cnt[n]; if (len > MAXDEG) len = MAXDEG;
    const int base = n * MAXDEG;
    const float dvn = rsqrtf((float)g_dv_cnt[n] * (1.f / DEG) + EPSf);
    const float alpha = g_alpha, beta = 1.f - alpha;
    float4 acc = make_float4(0.f, 0.f, 0.f, 0.f);
    for (int i = 0; i < len; i++) {
        int e = g_node_edges[base + i];
        float4 v = ((const float4*)&g_Medge[(size_t)e * HH])[lane];
        acc.x += v.x; acc.y += v.y; acc.z += v.z; acc.w += v.w;
    }
    float4 yv = ((const float4*)&g_y[(size_t)n * HH])[lane];
    float4 bg = ((const float4*)g_bg)[lane];
    ((float4*)&g_gp[(size_t)n * HH])[lane] =
        make_float4(alpha * yv.x + beta * dvn * acc.x + bg.x,
                    alpha * yv.y + beta * dvn * acc.y + bg.y,
                    alpha * yv.z + beta * dvn * acc.z + bg.z,
                    alpha * yv.w + beta * dvn * acc.w + bg.w);
}

// ---------------- tensor-core GEMM: double-buffered, packed hi/lo smem ----------------
__device__ __forceinline__ void mma_bf16(float* c, uint32_t a0, uint32_t a1,
                                         uint32_t a2, uint32_t a3,
                                         uint32_t b0, uint32_t b1) {
    asm volatile("mma.sync.aligned.m16n8k16.row.col.f32.bf16.bf16.f32 "
        "{%0,%1,%2,%3}, {%4,%5,%6,%7}, {%8,%9}, {%0,%1,%2,%3};"
        : "+f"(c[0]), "+f"(c[1]), "+f"(c[2]), "+f"(c[3])
        : "r"(a0), "r"(a1), "r"(a2), "r"(a3), "r"(b0), "r"(b1));
}
__device__ __forceinline__ void split2(float v0, float v1, uint32_t& hi, uint32_t& lo) {
    __nv_bfloat16 h0 = __float2bfloat16(v0), h1 = __float2bfloat16(v1);
    float l0 = v0 - __bfloat162float(h0);
    float l1 = v1 - __bfloat162float(h1);
    hi = (uint32_t)__bfloat16_as_ushort(h0) | ((uint32_t)__bfloat16_as_ushort(h1) << 16);
    lo = (uint32_t)__bfloat16_as_ushort(__float2bfloat16(l0))
       | ((uint32_t)__bfloat16_as_ushort(__float2bfloat16(l1)) << 16);
}

#define PST 40                 // u32 row stride
#define STG2 (192 * PST)       // u32 per stage
#define SMEM_BYTES (2 * STG2 * 4)

template <int MODE>
__global__ void __launch_bounds__(256)
tgemm(const float* __restrict__ Aext, const float* __restrict__ Bext,
      float* __restrict__ Cext, const float* __restrict__ bias) {
    constexpr int NCOLS = (MODE == 3) ? 200 : 128;
    constexpr int K     = (MODE == 1) ? 200 : 128;
    constexpr int LDA   = (MODE == 1) ? 200 : 128;
    constexpr int NCH   = (K + 31) / 32;

    extern __shared__ uint32_t sm[];

    const float* A = (MODE == 1) ? Aext
                   : (MODE == 2) ? (const float*)g_gp : (const float*)g_fused;
    const float* Bsrc = (MODE == 1) ? (const float*)g_Wg : Bext;
    float* C = (MODE == 1) ? (float*)g_y
             : (MODE == 2) ? (float*)g_fused : Cext;

    const int tid = threadIdx.x;
    const int lane = tid & 31;
    const int w = tid >> 5;
    const int wm = w & 3, wn = w >> 2;
    const int g = lane >> 2, tig = lane & 3;
    const int m0 = blockIdx.y * 128, n0 = blockIdx.x * 64;

    const int a_row = tid >> 3, a_kq = (tid & 7) * 4;
    const int b_m = tid & 15, b_nq = (tid >> 4) * 4;

    float acc[2][4][4];
#pragma unroll
    for (int mt = 0; mt < 2; mt++)
#pragma unroll
        for (int nt = 0; nt < 4; nt++)
#pragma unroll
            for (int j = 0; j < 4; j++) acc[mt][nt][j] = 0.f;

    const float4 z4 = make_float4(0.f, 0.f, 0.f, 0.f);
    float4 ar[4];
    float4 br0, br1;

    auto load_raw = [&](int k0) {
#pragma unroll
        for (int i = 0; i < 4; i++) {
            int row = a_row + i * 32;
            int gk = k0 + a_kq;
            ar[i] = (gk < K) ? *(const float4*)&A[(size_t)(m0 + row) * LDA + gk] : z4;
        }
        int gk0 = k0 + 2 * b_m, gk1 = gk0 + 1, gn = n0 + b_nq;
        br0 = (gk0 < K && gn < NCOLS) ? *(const float4*)&Bsrc[(size_t)gk0 * NCOLS + gn] : z4;
        br1 = (gk1 < K && gn < NCOLS) ? *(const float4*)&Bsrc[(size_t)gk1 * NCOLS + gn] : z4;
    };
    auto store_smem = [&](int buf) {
        uint32_t* Ap = sm + buf * STG2;
        uint32_t* Bp = Ap + 128 * PST;
#pragma unroll
        for (int i = 0; i < 4; i++) {
            int row = a_row + i * 32;
            uint32_t h0, l0, h1, l1;
            split2(ar[i].x, ar[i].y, h0, l0);
            split2(ar[i].z, ar[i].w, h1, l1);
            uint32_t* p = Ap + row * PST + a_kq;
            p[0] = h0; p[1] = l0; p[2] = h1; p[3] = l1;
        }
        float b0e[4] = {br0.x, br0.y, br0.z, br0.w};
        float b1e[4] = {br1.x, br1.y, br1.z, br1.w};
#pragma unroll
        for (int q = 0; q < 4; q++) {
            uint32_t hi, lo;
            split2(b0e[q], b1e[q], hi, lo);
            uint32_t* p = Bp + (b_nq + q) * PST + 2 * b_m;
            p[0] = hi; p[1] = lo;
        }
    };

    load_raw(0);
    store_smem(0);
    __syncthreads();

    for (int ch = 0; ch < NCH; ch++) {
        const int buf = ch & 1;
        const uint32_t* Ap = sm + buf * STG2;
        const uint32_t* Bp = Ap + 128 * PST;
        if (ch + 1 < NCH) load_raw((ch + 1) * 32);
#pragma unroll
        for (int ks = 0; ks < 32; ks += 16) {
            uint32_t ah[2][4], al[2][4];
#pragma unroll
            for (int mt = 0; mt < 2; mt++) {
                int r = wm * 32 + mt * 16 + g;
                uint2 p0 = *(const uint2*)(Ap + r * PST + ks + tig * 2);
                uint2 p1 = *(const uint2*)(Ap + (r + 8) * PST + ks + tig * 2);
                uint2 p2 = *(const uint2*)(Ap + r * PST + ks + tig * 2 + 8);
                uint2 p3 = *(const uint2*)(Ap + (r + 8) * PST + ks + tig * 2 + 8);
                ah[mt][0] = p0.x; al[mt][0] = p0.y;
                ah[mt][1] = p1.x; al[mt][1] = p1.y;
                ah[mt][2] = p2.x; al[mt][2] = p2.y;
                ah[mt][3] = p3.x; al[mt][3] = p3.y;
            }
            uint32_t bh[4][2], bl[4][2];
#pragma unroll
            for (int nt = 0; nt < 4; nt++) {
                int n = wn * 32 + nt * 8 + g;
                uint2 q0 = *(const uint2*)(Bp + n * PST + ks + tig * 2);
                uint2 q1 = *(const uint2*)(Bp + n * PST + ks + tig * 2 + 8);
                bh[nt][0] = q0.x; bl[nt][0] = q0.y;
                bh[nt][1] = q1.x; bl[nt][1] = q1.y;
            }
#pragma unroll
            for (int mt = 0; mt < 2; mt++)
#pragma unroll
                for (int nt = 0; nt < 4; nt++) {
                    mma_bf16(acc[mt][nt], ah[mt][0], ah[mt][1], ah[mt][2], ah[mt][3],
                             bh[nt][0], bh[nt][1]);
                    mma_bf16(acc[mt][nt], al[mt][0], al[mt][1], al[mt][2], al[mt][3],
                             bh[nt][0], bh[nt][1]);
                    mma_bf16(acc[mt][nt], ah[mt][0], ah[mt][1], ah[mt][2], ah[mt][3],
                             bl[nt][0], bl[nt][1]);
                }
        }
        if (ch + 1 < NCH) store_smem(buf ^ 1);
        __syncthreads();
    }

    // ---- epilogue ----
#pragma unroll
    for (int mt = 0; mt < 2; mt++) {
#pragma unroll
        for (int nt = 0; nt < 4; nt++) {
            int row = m0 + wm * 32 + mt * 16 + g;
            int col = n0 + wn * 32 + nt * 8 + tig * 2;
            if (col >= NCOLS) continue;
            float* cc = acc[mt][nt];
#pragma unroll
            for (int h = 0; h < 2; h++) {
                int r = row + h * 8;
                float v0 = cc[h * 2], v1 = cc[h * 2 + 1];
                if (MODE == 3) {
                    v0 += bias[col]; v1 += bias[col + 1];
                } else if (MODE == 2) {
                    int bi = r >> 11;  // Nn = 2048
                    float gp0 = g_gp[(size_t)r * HH + col];
                    float gp1 = g_gp[(size_t)r * HH + col + 1];
                    float gg0 = 1.f / (1.f + expf(-(v0 + g_cvec[bi * HH + col])));
                    float gg1 = 1.f / (1.f + expf(-(v1 + g_cvec[bi * HH + col + 1])));
                    v0 = gg0 * gp0 + (1.f - gg0) * g_att[bi * HH + col];
                    v1 = gg1 * gp1 + (1.f - gg1) * g_att[bi * HH + col + 1];
                }
                *(float2*)&C[(size_t)r * NCOLS + col] = make_float2(v0, v1);
            }
        }
    }
}

// ---------------- launcher (single stream, 9 nodes) ----------------
extern "C" void kernel_launch(void* const* d_in, const int* in_sizes, int n_in,
                              void* d_out, int out_size) {
    const float* x      = (const float*)d_in[0];
    const float* text   = (const float*)d_in[1];
    const float* W      = (const float*)d_in[2];
    const float* bvec   = (const float*)d_in[3];
    const float* gate_w = (const float*)d_in[4];
    const float* gate_b = (const float*)d_in[5];
    const float* gnn_w  = (const float*)d_in[6];
    const float* gnn_b  = (const float*)d_in[7];
    const float* text_w = (const float*)d_in[8];
    const float* text_b = (const float*)d_in[9];
    const float* in_w   = (const float*)d_in[10];
    const float* in_b   = (const float*)d_in[11];
    const float* aow    = (const float*)d_in[12];
    const float* aob    = (const float*)d_in[13];
    const float* fgw    = (const float*)d_in[14];
    const float* fgb    = (const float*)d_in[15];
    const float* outp_w = (const float*)d_in[16];
    const float* outp_b = (const float*)d_in[17];
    const int*   en     = (const int*)d_in[18];
    float* outp = (float*)d_out;

    static bool once = false;
    if (!once) {
        cudaFuncSetAttribute(tgemm<1>, cudaFuncAttributeMaxDynamicSharedMemorySize, SMEM_BYTES);
        cudaFuncSetAttribute(tgemm<2>, cudaFuncAttributeMaxDynamicSharedMemorySize, SMEM_BYTES);
        cudaFuncSetAttribute(tgemm<3>, cudaFuncAttributeMaxDynamicSharedMemorySize, SMEM_BYTES);
        once = true;
    }

    k_init<<<256, 256>>>(x, gate_w);

    // edge build (+ alpha finalize in block 0) ; sort
    k_edge_a<<<EE * DEG / 256, 256>>>(en, gate_b);
    k_sort<<<NN / 64, 64>>>();

    // Wg/bg precompute + per-batch attention constants (smem-staged, one wave)
    k_prec_const<<<30, 256>>>(W, gnn_w, gnn_b, bvec,
                              text, text_w, text_b, in_w, in_b, aow, aob, fgw, fgb);

    // y = x @ Wg  (tensor)
    tgemm<1><<<dim3(2, 64), 256, SMEM_BYTES>>>(x, nullptr, nullptr, nullptr);

    // sparse propagation on y (128 cols), gather writes gp directly
    k_edge_b<<<EE / 4, 128>>>(en);
    k_gather<<<NN / 8, 256>>>();

    // fused = sigmoid(gp @ fgate_w0 + c[b]) * gp + (1-g) * att[b]
    tgemm<2><<<dim3(2, 64), 256, SMEM_BYTES>>>(nullptr, fgw, nullptr, nullptr);

    // result = fused @ outp_w + outp_b
    tgemm<3><<<dim3(4, 64), 256, SMEM_BYTES>>>(nullptr, outp_w, outp, outp_b);
}

// round 14
// speedup vs baseline: 1.3919x; 1.3919x over previous
#include <cuda_runtime.h>
#include <cuda_bf16.h>
#include <math.h>
#include <stdint.h>

#define NN   8192
#define DD   200
#define BB   4
#define EE   4096
#define DEG  16
#define HH   128
#define EPSf 1e-8f
#define MAXDEG 64

// ---------------- scratch (device globals; no allocation allowed) ----------------
__device__ float g_y[NN * HH];        // x @ Wg
__device__ float g_Medge[EE * HH];
__device__ float g_gp[NN * HH];
__device__ float g_fused[NN * HH];
__device__ float g_Wg[DD * HH];       // W @ gnn_w
__device__ float g_bg[HH];            // b @ gnn_w + gnn_b
__device__ int   g_dv_cnt[NN];        // degree AND list cursor
__device__ int   g_de_cnt[EE];
__device__ unsigned g_maskbits[EE];
__device__ int   g_node_edges[NN * MAXDEG];
__device__ float g_alpha_part[256];
__device__ float g_alpha;
__device__ float g_att[BB * HH];
__device__ float g_cvec[BB * HH];

// ---------------- init: zero degree counters + alpha partial sums ----------------
__global__ void k_init(const float* __restrict__ x, const float* __restrict__ gw) {
    __shared__ float sm[256];
    int t = threadIdx.x;
    int gi = blockIdx.x * 256 + t;
    if (gi < NN) g_dv_cnt[gi] = 0;
    float s = 0.f;
    for (int i = gi; i < NN * DD; i += 256 * 256)
        s += x[i] * gw[i % DD];
    sm[t] = s; __syncthreads();
    for (int o = 128; o > 0; o >>= 1) { if (t < o) sm[t] += sm[t + o]; __syncthreads(); }
    if (t == 0) g_alpha_part[blockIdx.x] = sm[0];
}

// ---------------- edge pass: slot-parallel dedup + degree + list fill ----------------
// block 0 additionally finalizes alpha
__global__ void __launch_bounds__(256) k_edge_a(const int* __restrict__ en,
                                                const float* __restrict__ gb) {
    if (blockIdx.x == 0) {
        __shared__ float smf[256];
        int t = threadIdx.x;
        smf[t] = g_alpha_part[t]; __syncthreads();
        for (int o = 128; o > 0; o >>= 1) { if (t < o) smf[t] += smf[t + o]; __syncthreads(); }
        if (t == 0) g_alpha = 1.f / (1.f + expf(-(smf[0] / (float)NN + gb[0])));
    }
    const int gt   = blockIdx.x * 256 + threadIdx.x;   // 0 .. EE*DEG-1
    const int lane = threadIdx.x & 31;
    const int half = lane >> 4;
    const int s    = lane & 15;
    const int e    = (gt >> 5) * 2 + half;
    const int nd   = en[e * DEG + s];
    bool first = true;
#pragma unroll
    for (int j = 0; j < 15; j++) {
        int v = __shfl_sync(0xFFFFFFFFu, nd, (half << 4) + j);
        if (j < s && v == nd) first = false;
    }
    unsigned bal = __ballot_sync(0xFFFFFFFFu, first);
    unsigned m = (bal >> (half * 16)) & 0xFFFFu;
    if (s == 0) { g_maskbits[e] = m; g_de_cnt[e] = __popc(m); }
    if (first) {
        int p = atomicAdd(&g_dv_cnt[nd], 1);
        if (p < MAXDEG) g_node_edges[nd * MAXDEG + p] = e;
    }
}

// ---------------- sort node lists + per-batch constants (merged) ----------------
// blocks 0..63: sort 128 nodes each ; blocks 64..67: const chain for batch (bx-64)
__global__ void __launch_bounds__(128) k_sort_const(
        const float* __restrict__ text,
        const float* __restrict__ text_w, const float* __restrict__ text_b,
        const float* __restrict__ in_w,   const float* __restrict__ in_b,
        const float* __restrict__ aow,    const float* __restrict__ aob,
        const float* __restrict__ fgw,    const float* __restrict__ fgb) {
    const int tid = threadIdx.x;
    if (blockIdx.x < 64) {
        int n = blockIdx.x * 128 + tid;
        int len = g_dv_cnt[n]; if (len > MAXDEG) len = MAXDEG;
        int* a = &g_node_edges[n * MAXDEG];
        for (int i = 1; i < len; i++) {
            int key = a[i]; int j = i - 1;
            while (j >= 0 && a[j] > key) { a[j + 1] = a[j]; j--; }
            a[j + 1] = key;
        }
        return;
    }
    // ---- per-batch constants (R10-proven body) ----
    __shared__ float tp[HH];
    __shared__ float vv[HH];
    __shared__ float at[HH];
    int b = blockIdx.x - 64;
    int j = tid;
    {
        float s = text_b[j];
        for (int k = 0; k < DD; k++) s += text[b * DD + k] * text_w[k * HH + j];
        tp[j] = s;
    }
    __syncthreads();
    {
        float s = in_b[2 * HH + j];
        for (int k = 0; k < HH; k++) s += tp[k] * in_w[k * 3 * HH + 2 * HH + j];
        vv[j] = s;
    }
    __syncthreads();
    {
        float s = aob[j];
        for (int k = 0; k < HH; k++) s += vv[k] * aow[k * HH + j];
        at[j] = s;
        g_att[b * HH + j] = s;
    }
    __syncthreads();
    {
        float s = fgb[j];
        for (int k = 0; k < HH; k++) s += at[k] * fgw[(HH + k) * HH + j];
        g_cvec[b * HH + j] = s;
    }
}

// Medge[e,:] over y (128 cols); 4 edges/block, 32 lanes/edge
__global__ void __launch_bounds__(128) k_edge_b(const int* __restrict__ en) {
    __shared__ int   sn[4][DEG];
    __shared__ float sw[4][DEG];
    const int tid = threadIdx.x;
    const int sub = tid >> 5, lane = tid & 31;
    const int e0 = blockIdx.x * 4;
    if (tid < 64) {
        int ee = tid >> 4, s = tid & 15;
        int e = e0 + ee;
        int n = en[e * DEG + s];
        sn[ee][s] = n;
        sw[ee][s] = ((g_maskbits[e] >> s) & 1u)
                      ? rsqrtf((float)g_dv_cnt[n] * (1.f / DEG) + EPSf) : 0.f;
    }
    __syncthreads();
    const int e = e0 + sub;
    float4 acc = make_float4(0.f, 0.f, 0.f, 0.f);
#pragma unroll
    for (int s = 0; s < DEG; s++) {
        float w = sw[sub][s];
        float4 v = ((const float4*)&g_y[(size_t)sn[sub][s] * HH])[lane];
        acc.x += w * v.x; acc.y += w * v.y; acc.z += w * v.z; acc.w += w * v.w;
    }
    float sc = 1.f / ((float)g_de_cnt[e] * (1.f / DEG) + EPSf) * (1.f / (DEG * DEG));
    ((float4*)&g_Medge[(size_t)e * HH])[lane] =
        make_float4(acc.x * sc, acc.y * sc, acc.z * sc, acc.w * sc);
}

// gp = alpha*y + (1-alpha)*dv*sum Medge + bg ; 8 nodes/block (warp per node)
__global__ void __launch_bounds__(256) k_gather() {
    const int n = blockIdx.x * 8 + (threadIdx.x >> 5);
    const int lane = threadIdx.x & 31;
    int len  = g_dv_cnt[n]; if (len > MAXDEG) len = MAXDEG;
    const int base = n * MAXDEG;
    const float dvn = rsqrtf((float)g_dv_cnt[n] * (1.f / DEG) + EPSf);
    const float alpha = g_alpha, beta = 1.f - alpha;
    float4 acc = make_float4(0.f, 0.f, 0.f, 0.f);
    for (int i = 0; i < len; i++) {
        int e = g_node_edges[base + i];
        float4 v = ((const float4*)&g_Medge[(size_t)e * HH])[lane];
        acc.x += v.x; acc.y += v.y; acc.z += v.z; acc.w += v.w;
    }
    float4 yv = ((const float4*)&g_y[(size_t)n * HH])[lane];
    float4 bg = ((const float4*)g_bg)[lane];
    ((float4*)&g_gp[(size_t)n * HH])[lane] =
        make_float4(alpha * yv.x + beta * dvn * acc.x + bg.x,
                    alpha * yv.y + beta * dvn * acc.y + bg.y,
                    alpha * yv.z + beta * dvn * acc.z + bg.z,
                    alpha * yv.w + beta * dvn * acc.w + bg.w);
}

// ---------------- tensor-core GEMM: double-buffered, packed hi/lo smem ----------------
// MODE 0: [W;b] @ gnn_w -> g_Wg / g_bg(+gnn_b)  (A row-guarded)
// MODE 1: g_y = x @ g_Wg ; 2: g_fused = gate epi ; 3: Cext = g_fused @ outp_w + bias
__device__ __forceinline__ void mma_bf16(float* c, uint32_t a0, uint32_t a1,
                                         uint32_t a2, uint32_t a3,
                                         uint32_t b0, uint32_t b1) {
    asm volatile("mma.sync.aligned.m16n8k16.row.col.f32.bf16.bf16.f32 "
        "{%0,%1,%2,%3}, {%4,%5,%6,%7}, {%8,%9}, {%0,%1,%2,%3};"
        : "+f"(c[0]), "+f"(c[1]), "+f"(c[2]), "+f"(c[3])
        : "r"(a0), "r"(a1), "r"(a2), "r"(a3), "r"(b0), "r"(b1));
}
__device__ __forceinline__ void split2(float v0, float v1, uint32_t& hi, uint32_t& lo) {
    __nv_bfloat16 h0 = __float2bfloat16(v0), h1 = __float2bfloat16(v1);
    float l0 = v0 - __bfloat162float(h0);
    float l1 = v1 - __bfloat162float(h1);
    hi = (uint32_t)__bfloat16_as_ushort(h0) | ((uint32_t)__bfloat16_as_ushort(h1) << 16);
    lo = (uint32_t)__bfloat16_as_ushort(__float2bfloat16(l0))
       | ((uint32_t)__bfloat16_as_ushort(__float2bfloat16(l1)) << 16);
}

#define PST 40                 // u32 row stride
#define STG2 (192 * PST)       // u32 per stage
#define SMEM_BYTES (2 * STG2 * 4)

template <int MODE>
__global__ void __launch_bounds__(256)
tgemm(const float* __restrict__ Aext, const float* __restrict__ Bext,
      float* __restrict__ Cext, const float* __restrict__ bias,
      const float* __restrict__ aux) {
    constexpr int NCOLS = (MODE == 3) ? 200 : 128;
    constexpr int K     = (MODE <= 1) ? 200 : 128;
    constexpr int LDA   = (MODE <= 1) ? 200 : 128;
    constexpr int NCH   = (K + 31) / 32;

    extern __shared__ uint32_t sm[];

    const float* A = (MODE <= 1) ? Aext
                   : (MODE == 2) ? (const float*)g_gp : (const float*)g_fused;
    const float* Bsrc = (MODE == 1) ? (const float*)g_Wg : Bext;
    float* C = (MODE == 0) ? (float*)g_Wg
             : (MODE == 1) ? (float*)g_y
             : (MODE == 2) ? (float*)g_fused : Cext;

    const int tid = threadIdx.x;
    const int lane = tid & 31;
    const int w = tid >> 5;
    const int wm = w & 3, wn = w >> 2;
    const int g = lane >> 2, tig = lane & 3;
    const int m0 = blockIdx.y * 128, n0 = blockIdx.x * 64;

    const int a_row = tid >> 3, a_kq = (tid & 7) * 4;
    const int b_m = tid & 15, b_nq = (tid >> 4) * 4;

    float acc[2][4][4];
#pragma unroll
    for (int mt = 0; mt < 2; mt++)
#pragma unroll
        for (int nt = 0; nt < 4; nt++)
#pragma unroll
            for (int j = 0; j < 4; j++) acc[mt][nt][j] = 0.f;

    const float4 z4 = make_float4(0.f, 0.f, 0.f, 0.f);
    float4 ar[4];
    float4 br0, br1;

    auto load_raw = [&](int k0) {
#pragma unroll
        for (int i = 0; i < 4; i++) {
            int row = a_row + i * 32;
            int gk = k0 + a_kq;
            if (gk >= K) { ar[i] = z4; continue; }
            if (MODE == 0) {
                int r = m0 + row;
                if (r < DD)       ar[i] = *(const float4*)&A[(size_t)r * DD + gk];
                else if (r == DD) ar[i] = *(const float4*)&aux[gk];
                else              ar[i] = z4;
            } else {
                ar[i] = *(const float4*)&A[(size_t)(m0 + row) * LDA + gk];
            }
        }
        int gk0 = k0 + 2 * b_m, gk1 = gk0 + 1, gn = n0 + b_nq;
        br0 = (gk0 < K && gn < NCOLS) ? *(const float4*)&Bsrc[(size_t)gk0 * NCOLS + gn] : z4;
        br1 = (gk1 < K && gn < NCOLS) ? *(const float4*)&Bsrc[(size_t)gk1 * NCOLS + gn] : z4;
    };
    auto store_smem = [&](int buf) {
        uint32_t* Ap = sm + buf * STG2;
        uint32_t* Bp = Ap + 128 * PST;
#pragma unroll
        for (int i = 0; i < 4; i++) {
            int row = a_row + i * 32;
            uint32_t h0, l0, h1, l1;
            split2(ar[i].x, ar[i].y, h0, l0);
            split2(ar[i].z, ar[i].w, h1, l1);
            uint32_t* p = Ap + row * PST + a_kq;
            p[0] = h0; p[1] = l0; p[2] = h1; p[3] = l1;
        }
        float b0e[4] = {br0.x, br0.y, br0.z, br0.w};
        float b1e[4] = {br1.x, br1.y, br1.z, br1.w};
#pragma unroll
        for (int q = 0; q < 4; q++) {
            uint32_t hi, lo;
            split2(b0e[q], b1e[q], hi, lo);
            uint32_t* p = Bp + (b_nq + q) * PST + 2 * b_m;
            p[0] = hi; p[1] = lo;
        }
    };

    load_raw(0);
    store_smem(0);
    __syncthreads();

    for (int ch = 0; ch < NCH; ch++) {
        const int buf = ch & 1;
        const uint32_t* Ap = sm + buf * STG2;
        const uint32_t* Bp = Ap + 128 * PST;
        if (ch + 1 < NCH) load_raw((ch + 1) * 32);
#pragma unroll
        for (int ks = 0; ks < 32; ks += 16) {
            uint32_t ah[2][4], al[2][4];
#pragma unroll
            for (int mt = 0; mt < 2; mt++) {
                int r = wm * 32 + mt * 16 + g;
                uint2 p0 = *(const uint2*)(Ap + r * PST + ks + tig * 2);
                uint2 p1 = *(const uint2*)(Ap + (r + 8) * PST + ks + tig * 2);
                uint2 p2 = *(const uint2*)(Ap + r * PST + ks + tig * 2 + 8);
                uint2 p3 = *(const uint2*)(Ap + (r + 8) * PST + ks + tig * 2 + 8);
                ah[mt][0] = p0.x; al[mt][0] = p0.y;
                ah[mt][1] = p1.x; al[mt][1] = p1.y;
                ah[mt][2] = p2.x; al[mt][2] = p2.y;
                ah[mt][3] = p3.x; al[mt][3] = p3.y;
            }
            uint32_t bh[4][2], bl[4][2];
#pragma unroll
            for (int nt = 0; nt < 4; nt++) {
                int n = wn * 32 + nt * 8 + g;
                uint2 q0 = *(const uint2*)(Bp + n * PST + ks + tig * 2);
                uint2 q1 = *(const uint2*)(Bp + n * PST + ks + tig * 2 + 8);
                bh[nt][0] = q0.x; bl[nt][0] = q0.y;
                bh[nt][1] = q1.x; bl[nt][1] = q1.y;
            }
#pragma unroll
            for (int mt = 0; mt < 2; mt++)
#pragma unroll
                for (int nt = 0; nt < 4; nt++) {
                    mma_bf16(acc[mt][nt], ah[mt][0], ah[mt][1], ah[mt][2], ah[mt][3],
                             bh[nt][0], bh[nt][1]);
                    mma_bf16(acc[mt][nt], al[mt][0], al[mt][1], al[mt][2], al[mt][3],
                             bh[nt][0], bh[nt][1]);
                    mma_bf16(acc[mt][nt], ah[mt][0], ah[mt][1], ah[mt][2], ah[mt][3],
                             bl[nt][0], bl[nt][1]);
                }
        }
        if (ch + 1 < NCH) store_smem(buf ^ 1);
        __syncthreads();
    }

    // ---- epilogue ----
#pragma unroll
    for (int mt = 0; mt < 2; mt++) {
#pragma unroll
        for (int nt = 0; nt < 4; nt++) {
            int row = m0 + wm * 32 + mt * 16 + g;
            int col = n0 + wn * 32 + nt * 8 + tig * 2;
            if (col >= NCOLS) continue;
            float* cc = acc[mt][nt];
#pragma unroll
            for (int h = 0; h < 2; h++) {
                int r = row + h * 8;
                float v0 = cc[h * 2], v1 = cc[h * 2 + 1];
                if (MODE == 0) {
                    if (r < DD) {
                        *(float2*)&C[(size_t)r * HH + col] = make_float2(v0, v1);
                    } else if (r == DD) {
                        g_bg[col]     = v0 + bias[col];
                        g_bg[col + 1] = v1 + bias[col + 1];
                    }
                    continue;
                }
                if (MODE == 3) {
                    v0 += bias[col]; v1 += bias[col + 1];
                } else if (MODE == 2) {
                    int bi = r >> 11;  // Nn = 2048
                    float gp0 = g_gp[(size_t)r * HH + col];
                    float gp1 = g_gp[(size_t)r * HH + col + 1];
                    float gg0 = 1.f / (1.f + expf(-(v0 + g_cvec[bi * HH + col])));
                    float gg1 = 1.f / (1.f + expf(-(v1 + g_cvec[bi * HH + col + 1])));
                    v0 = gg0 * gp0 + (1.f - gg0) * g_att[bi * HH + col];
                    v1 = gg1 * gp1 + (1.f - gg1) * g_att[bi * HH + col + 1];
                }
                *(float2*)&C[(size_t)r * NCOLS + col] = make_float2(v0, v1);
            }
        }
    }
}

// ---------------- launcher (single stream, 9 nodes) ----------------
extern "C" void kernel_launch(void* const* d_in, const int* in_sizes, int n_in,
                              void* d_out, int out_size) {
    const float* x      = (const float*)d_in[0];
    const float* text   = (const float*)d_in[1];
    const float* W      = (const float*)d_in[2];
    const float* bvec   = (const float*)d_in[3];
    const float* gate_w = (const float*)d_in[4];
    const float* gate_b = (const float*)d_in[5];
    const float* gnn_w  = (const float*)d_in[6];
    const float* gnn_b  = (const float*)d_in[7];
    const float* text_w = (const float*)d_in[8];
    const float* text_b = (const float*)d_in[9];
    const float* in_w   = (const float*)d_in[10];
    const float* in_b   = (const float*)d_in[11];
    const float* aow    = (const float*)d_in[12];
    const float* aob    = (const float*)d_in[13];
    const float* fgw    = (const float*)d_in[14];
    const float* fgb    = (const float*)d_in[15];
    const float* outp_w = (const float*)d_in[16];
    const float* outp_b = (const float*)d_in[17];
    const int*   en     = (const int*)d_in[18];
    float* outp = (float*)d_out;

    static bool once = false;
    if (!once) {
        cudaFuncSetAttribute(tgemm<0>, cudaFuncAttributeMaxDynamicSharedMemorySize, SMEM_BYTES);
        cudaFuncSetAttribute(tgemm<1>, cudaFuncAttributeMaxDynamicSharedMemorySize, SMEM_BYTES);
        cudaFuncSetAttribute(tgemm<2>, cudaFuncAttributeMaxDynamicSharedMemorySize, SMEM_BYTES);
        cudaFuncSetAttribute(tgemm<3>, cudaFuncAttributeMaxDynamicSharedMemorySize, SMEM_BYTES);
        once = true;
    }

    k_init<<<256, 256>>>(x, gate_w);

    // edge build (+ alpha finalize in block 0)
    k_edge_a<<<EE * DEG / 256, 256>>>(en, gate_b);

    // sort node lists + per-batch attention constants (merged)
    k_sort_const<<<68, 128>>>(text, text_w, text_b, in_w, in_b, aow, aob, fgw, fgb);

    // Wg = [W; b] @ gnn_w (tensor, row-guarded)
    tgemm<0><<<dim3(2, 2), 256, SMEM_BYTES>>>(W, gnn_w, nullptr, gnn_b, bvec);

    // y = x @ Wg  (tensor)
    tgemm<1><<<dim3(2, 64), 256, SMEM_BYTES>>>(x, nullptr, nullptr, nullptr, nullptr);

    // sparse propagation on y (128 cols), gather writes gp directly
    k_edge_b<<<EE / 4, 128>>>(en);
    k_gather<<<NN / 8, 256>>>();

    // fused = sigmoid(gp @ fgate_w0 + c[b]) * gp + (1-g) * att[b]
    tgemm<2><<<dim3(2, 64), 256, SMEM_BYTES>>>(nullptr, fgw, nullptr, nullptr, nullptr);

    // result = fused @ outp_w + outp_b
    tgemm<3><<<dim3(4, 64), 256, SMEM_BYTES>>>(nullptr, outp_w, outp, outp_b, nullptr);
}

// round 15
// speedup vs baseline: 1.4678x; 1.0546x over previous
#include <cuda_runtime.h>
#include <cuda_bf16.h>
#include <math.h>
#include <stdint.h>

#define NN   8192
#define DD   200
#define BB   4
#define EE   4096
#define DEG  16
#define HH   128
#define EPSf 1e-8f
#define MAXDEG 64

// ---------------- scratch (device globals; no allocation allowed) ----------------
__device__ float g_y[NN * HH];        // x @ Wg
__device__ float g_Medge[EE * HH];
__device__ float g_gp[NN * HH];
__device__ float g_fused[NN * HH];
__device__ float g_Wg[DD * HH];       // W @ gnn_w
__device__ float g_bg[HH];            // b @ gnn_w + gnn_b
__device__ int   g_dv_cnt[NN];        // degree AND list cursor
__device__ int   g_de_cnt[EE];
__device__ unsigned g_maskbits[EE];
__device__ int   g_node_edges[NN * MAXDEG];
__device__ float g_alpha_part[256];
__device__ float g_alpha;
__device__ float g_att[BB * HH];
__device__ float g_cvec[BB * HH];

// ---------------- edge pass: slot-parallel dedup + degree + list fill ----------------
// block 0 additionally finalizes alpha (g_alpha_part written by fused tgemm<0> init blocks)
__global__ void __launch_bounds__(256) k_edge_a(const int* __restrict__ en,
                                                const float* __restrict__ gb) {
    if (blockIdx.x == 0) {
        __shared__ float smf[256];
        int t = threadIdx.x;
        smf[t] = g_alpha_part[t]; __syncthreads();
        for (int o = 128; o > 0; o >>= 1) { if (t < o) smf[t] += smf[t + o]; __syncthreads(); }
        if (t == 0) g_alpha = 1.f / (1.f + expf(-(smf[0] / (float)NN + gb[0])));
    }
    const int gt   = blockIdx.x * 256 + threadIdx.x;   // 0 .. EE*DEG-1
    const int lane = threadIdx.x & 31;
    const int half = lane >> 4;
    const int s    = lane & 15;
    const int e    = (gt >> 5) * 2 + half;
    const int nd   = en[e * DEG + s];
    bool first = true;
#pragma unroll
    for (int j = 0; j < 15; j++) {
        int v = __shfl_sync(0xFFFFFFFFu, nd, (half << 4) + j);
        if (j < s && v == nd) first = false;
    }
    unsigned bal = __ballot_sync(0xFFFFFFFFu, first);
    unsigned m = (bal >> (half * 16)) & 0xFFFFu;
    if (s == 0) { g_maskbits[e] = m; g_de_cnt[e] = __popc(m); }
    if (first) {
        int p = atomicAdd(&g_dv_cnt[nd], 1);
        if (p < MAXDEG) g_node_edges[nd * MAXDEG + p] = e;
    }
}

// ---------------- edge_b + sort + per-batch consts (fused, 128 thr) ----------------
// blocks 0..1023: Medge ; 1024..1087: sort 128 nodes each ; 1088..1091: const chain
__global__ void __launch_bounds__(128) k_edge_bsc(
        const int* __restrict__ en,
        const float* __restrict__ text,
        const float* __restrict__ text_w, const float* __restrict__ text_b,
        const float* __restrict__ in_w,   const float* __restrict__ in_b,
        const float* __restrict__ aow,    const float* __restrict__ aob,
        const float* __restrict__ fgw,    const float* __restrict__ fgb) {
    const int tid = threadIdx.x;
    if (blockIdx.x >= 1088) {
        // ---- per-batch constants (proven serial body) ----
        __shared__ float tp[HH];
        __shared__ float vv[HH];
        __shared__ float at[HH];
        int b = blockIdx.x - 1088;
        int j = tid;
        {
            float s = text_b[j];
            for (int k = 0; k < DD; k++) s += text[b * DD + k] * text_w[k * HH + j];
            tp[j] = s;
        }
        __syncthreads();
        {
            float s = in_b[2 * HH + j];
            for (int k = 0; k < HH; k++) s += tp[k] * in_w[k * 3 * HH + 2 * HH + j];
            vv[j] = s;
        }
        __syncthreads();
        {
            float s = aob[j];
            for (int k = 0; k < HH; k++) s += vv[k] * aow[k * HH + j];
            at[j] = s;
            g_att[b * HH + j] = s;
        }
        __syncthreads();
        {
            float s = fgb[j];
            for (int k = 0; k < HH; k++) s += at[k] * fgw[(HH + k) * HH + j];
            g_cvec[b * HH + j] = s;
        }
        return;
    }
    if (blockIdx.x >= 1024) {
        // ---- sort node edge lists ----
        int n = (blockIdx.x - 1024) * 128 + tid;
        int len = g_dv_cnt[n]; if (len > MAXDEG) len = MAXDEG;
        int* a = &g_node_edges[n * MAXDEG];
        for (int i = 1; i < len; i++) {
            int key = a[i]; int j = i - 1;
            while (j >= 0 && a[j] > key) { a[j + 1] = a[j]; j--; }
            a[j + 1] = key;
        }
        return;
    }
    // ---- Medge[e,:] over y (128 cols); 4 edges/block, 32 lanes/edge ----
    __shared__ int   sn[4][DEG];
    __shared__ float sw[4][DEG];
    const int sub = tid >> 5, lane = tid & 31;
    const int e0 = blockIdx.x * 4;
    if (tid < 64) {
        int ee = tid >> 4, s = tid & 15;
        int e = e0 + ee;
        int n = en[e * DEG + s];
        sn[ee][s] = n;
        sw[ee][s] = ((g_maskbits[e] >> s) & 1u)
                      ? rsqrtf((float)g_dv_cnt[n] * (1.f / DEG) + EPSf) : 0.f;
    }
    __syncthreads();
    const int e = e0 + sub;
    float4 acc = make_float4(0.f, 0.f, 0.f, 0.f);
#pragma unroll
    for (int s = 0; s < DEG; s++) {
        float w = sw[sub][s];
        float4 v = ((const float4*)&g_y[(size_t)sn[sub][s] * HH])[lane];
        acc.x += w * v.x; acc.y += w * v.y; acc.z += w * v.z; acc.w += w * v.w;
    }
    float sc = 1.f / ((float)g_de_cnt[e] * (1.f / DEG) + EPSf) * (1.f / (DEG * DEG));
    ((float4*)&g_Medge[(size_t)e * HH])[lane] =
        make_float4(acc.x * sc, acc.y * sc, acc.z * sc, acc.w * sc);
}

// gp = alpha*y + (1-alpha)*dv*sum Medge + bg ; 8 nodes/block (warp per node)
__global__ void __launch_bounds__(256) k_gather() {
    const int n = blockIdx.x * 8 + (threadIdx.x >> 5);
    const int lane = threadIdx.x & 31;
    int len  = g_dv_cnt[n]; if (len > MAXDEG) len = MAXDEG;
    const int base = n * MAXDEG;
    const float dvn = rsqrtf((float)g_dv_cnt[n] * (1.f / DEG) + EPSf);
    const float alpha = g_alpha, beta = 1.f - alpha;
    float4 acc = make_float4(0.f, 0.f, 0.f, 0.f);
    for (int i = 0; i < len; i++) {
        int e = g_node_edges[base + i];
        float4 v = ((const float4*)&g_Medge[(size_t)e * HH])[lane];
        acc.x += v.x; acc.y += v.y; acc.z += v.z; acc.w += v.w;
    }
    float4 yv = ((const float4*)&g_y[(size_t)n * HH])[lane];
    float4 bg = ((const float4*)g_bg)[lane];
    ((float4*)&g_gp[(size_t)n * HH])[lane] =
        make_float4(alpha * yv.x + beta * dvn * acc.x + bg.x,
                    alpha * yv.y + beta * dvn * acc.y + bg.y,
                    alpha * yv.z + beta * dvn * acc.z + bg.z,
                    alpha * yv.w + beta * dvn * acc.w + bg.w);
}

// ---------------- tensor-core GEMM: double-buffered, packed hi/lo smem ----------------
// MODE 0: blocks 0..3 = [W;b]@gnn_w -> Wg/bg ; blocks 4..259 = k_init body
// MODE 1: g_y = x @ g_Wg ; 2: g_fused = gate epi ; 3: Cext = g_fused @ outp_w + bias
__device__ __forceinline__ void mma_bf16(float* c, uint32_t a0, uint32_t a1,
                                         uint32_t a2, uint32_t a3,
                                         uint32_t b0, uint32_t b1) {
    asm volatile("mma.sync.aligned.m16n8k16.row.col.f32.bf16.bf16.f32 "
        "{%0,%1,%2,%3}, {%4,%5,%6,%7}, {%8,%9}, {%0,%1,%2,%3};"
        : "+f"(c[0]), "+f"(c[1]), "+f"(c[2]), "+f"(c[3])
        : "r"(a0), "r"(a1), "r"(a2), "r"(a3), "r"(b0), "r"(b1));
}
__device__ __forceinline__ void split2(float v0, float v1, uint32_t& hi, uint32_t& lo) {
    __nv_bfloat16 h0 = __float2bfloat16(v0), h1 = __float2bfloat16(v1);
    float l0 = v0 - __bfloat162float(h0);
    float l1 = v1 - __bfloat162float(h1);
    hi = (uint32_t)__bfloat16_as_ushort(h0) | ((uint32_t)__bfloat16_as_ushort(h1) << 16);
    lo = (uint32_t)__bfloat16_as_ushort(__float2bfloat16(l0))
       | ((uint32_t)__bfloat16_as_ushort(__float2bfloat16(l1)) << 16);
}

#define PST 40                 // u32 row stride
#define STG2 (192 * PST)       // u32 per stage
#define SMEM_BYTES (2 * STG2 * 4)

template <int MODE>
__global__ void __launch_bounds__(256)
tgemm(const float* __restrict__ Aext, const float* __restrict__ Bext,
      float* __restrict__ Cext, const float* __restrict__ bias,
      const float* __restrict__ aux,
      const float* __restrict__ xp, const float* __restrict__ gwp) {
    constexpr int NCOLS = (MODE == 3) ? 200 : 128;
    constexpr int K     = (MODE <= 1) ? 200 : 128;
    constexpr int LDA   = (MODE <= 1) ? 200 : 128;
    constexpr int NCH   = (K + 31) / 32;

    extern __shared__ uint32_t sm[];

    if (MODE == 0 && blockIdx.x >= 4) {
        // ===== k_init body: zero dv_cnt + alpha partial sums =====
        float* smf = (float*)sm;
        int t = threadIdx.x;
        int bb = blockIdx.x - 4;              // 0..255
        int gi = bb * 256 + t;
        if (gi < NN) g_dv_cnt[gi] = 0;
        float s = 0.f;
        for (int i = gi; i < NN * DD; i += 256 * 256)
            s += xp[i] * gwp[i % DD];
        smf[t] = s; __syncthreads();
        for (int o = 128; o > 0; o >>= 1) { if (t < o) smf[t] += smf[t + o]; __syncthreads(); }
        if (t == 0) g_alpha_part[bb] = smf[0];
        return;
    }

    const float* A = (MODE <= 1) ? Aext
                   : (MODE == 2) ? (const float*)g_gp : (const float*)g_fused;
    const float* Bsrc = (MODE == 1) ? (const float*)g_Wg : Bext;
    float* C = (MODE == 0) ? (float*)g_Wg
             : (MODE == 1) ? (float*)g_y
             : (MODE == 2) ? (float*)g_fused : Cext;

    const int tid = threadIdx.x;
    const int lane = tid & 31;
    const int w = tid >> 5;
    const int wm = w & 3, wn = w >> 2;
    const int g = lane >> 2, tig = lane & 3;
    const int m0 = (MODE == 0) ? (int)(blockIdx.x >> 1) * 128 : blockIdx.y * 128;
    const int n0 = (MODE == 0) ? (int)(blockIdx.x & 1) * 64  : blockIdx.x * 64;

    const int a_row = tid >> 3, a_kq = (tid & 7) * 4;
    const int b_m = tid & 15, b_nq = (tid >> 4) * 4;

    float acc[2][4][4];
#pragma unroll
    for (int mt = 0; mt < 2; mt++)
#pragma unroll
        for (int nt = 0; nt < 4; nt++)
#pragma unroll
            for (int j = 0; j < 4; j++) acc[mt][nt][j] = 0.f;

    const float4 z4 = make_float4(0.f, 0.f, 0.f, 0.f);
    float4 ar[4];
    float4 br0, br1;

    auto load_raw = [&](int k0) {
#pragma unroll
        for (int i = 0; i < 4; i++) {
            int row = a_row + i * 32;
            int gk = k0 + a_kq;
            if (gk >= K) { ar[i] = z4; continue; }
            if (MODE == 0) {
                int r = m0 + row;
                if (r < DD)       ar[i] = *(const float4*)&A[(size_t)r * DD + gk];
                else if (r == DD) ar[i] = *(const float4*)&aux[gk];
                else              ar[i] = z4;
            } else {
                ar[i] = *(const float4*)&A[(size_t)(m0 + row) * LDA + gk];
            }
        }
        int gk0 = k0 + 2 * b_m, gk1 = gk0 + 1, gn = n0 + b_nq;
        br0 = (gk0 < K && gn < NCOLS) ? *(const float4*)&Bsrc[(size_t)gk0 * NCOLS + gn] : z4;
        br1 = (gk1 < K && gn < NCOLS) ? *(const float4*)&Bsrc[(size_t)gk1 * NCOLS + gn] : z4;
    };
    auto store_smem = [&](int buf) {
        uint32_t* Ap = sm + buf * STG2;
        uint32_t* Bp = Ap + 128 * PST;
#pragma unroll
        for (int i = 0; i < 4; i++) {
            int row = a_row + i * 32;
            uint32_t h0, l0, h1, l1;
            split2(ar[i].x, ar[i].y, h0, l0);
            split2(ar[i].z, ar[i].w, h1, l1);
            uint32_t* p = Ap + row * PST + a_kq;
            p[0] = h0; p[1] = l0; p[2] = h1; p[3] = l1;
        }
        float b0e[4] = {br0.x, br0.y, br0.z, br0.w};
        float b1e[4] = {br1.x, br1.y, br1.z, br1.w};
#pragma unroll
        for (int q = 0; q < 4; q++) {
            uint32_t hi, lo;
            split2(b0e[q], b1e[q], hi, lo);
            uint32_t* p = Bp + (b_nq + q) * PST + 2 * b_m;
            p[0] = hi; p[1] = lo;
        }
    };

    load_raw(0);
    store_smem(0);
    __syncthreads();

    for (int ch = 0; ch < NCH; ch++) {
        const int buf = ch & 1;
        const uint32_t* Ap = sm + buf * STG2;
        const uint32_t* Bp = Ap + 128 * PST;
        if (ch + 1 < NCH) load_raw((ch + 1) * 32);
#pragma unroll
        for (int ks = 0; ks < 32; ks += 16) {
            uint32_t ah[2][4], al[2][4];
#pragma unroll
            for (int mt = 0; mt < 2; mt++) {
                int r = wm * 32 + mt * 16 + g;
                uint2 p0 = *(const uint2*)(Ap + r * PST + ks + tig * 2);
                uint2 p1 = *(const uint2*)(Ap + (r + 8) * PST + ks + tig * 2);
                uint2 p2 = *(const uint2*)(Ap + r * PST + ks + tig * 2 + 8);
                uint2 p3 = *(const uint2*)(Ap + (r + 8) * PST + ks + tig * 2 + 8);
                ah[mt][0] = p0.x; al[mt][0] = p0.y;
                ah[mt][1] = p1.x; al[mt][1] = p1.y;
                ah[mt][2] = p2.x; al[mt][2] = p2.y;
                ah[mt][3] = p3.x; al[mt][3] = p3.y;
            }
            uint32_t bh[4][2], bl[4][2];
#pragma unroll
            for (int nt = 0; nt < 4; nt++) {
                int n = wn * 32 + nt * 8 + g;
                uint2 q0 = *(const uint2*)(Bp + n * PST + ks + tig * 2);
                uint2 q1 = *(const uint2*)(Bp + n * PST + ks + tig * 2 + 8);
                bh[nt][0] = q0.x; bl[nt][0] = q0.y;
                bh[nt][1] = q1.x; bl[nt][1] = q1.y;
            }
#pragma unroll
            for (int mt = 0; mt < 2; mt++)
#pragma unroll
                for (int nt = 0; nt < 4; nt++) {
                    mma_bf16(acc[mt][nt], ah[mt][0], ah[mt][1], ah[mt][2], ah[mt][3],
                             bh[nt][0], bh[nt][1]);
                    mma_bf16(acc[mt][nt], al[mt][0], al[mt][1], al[mt][2], al[mt][3],
                             bh[nt][0], bh[nt][1]);
                    mma_bf16(acc[mt][nt], ah[mt][0], ah[mt][1], ah[mt][2], ah[mt][3],
                             bl[nt][0], bl[nt][1]);
                }
        }
        if (ch + 1 < NCH) store_smem(buf ^ 1);
        __syncthreads();
    }

    // ---- epilogue ----
#pragma unroll
    for (int mt = 0; mt < 2; mt++) {
#pragma unroll
        for (int nt = 0; nt < 4; nt++) {
            int row = m0 + wm * 32 + mt * 16 + g;
            int col = n0 + wn * 32 + nt * 8 + tig * 2;
            if (col >= NCOLS) continue;
            float* cc = acc[mt][nt];
#pragma unroll
            for (int h = 0; h < 2; h++) {
                int r = row + h * 8;
                float v0 = cc[h * 2], v1 = cc[h * 2 + 1];
                if (MODE == 0) {
                    if (r < DD) {
                        *(float2*)&C[(size_t)r * HH + col] = make_float2(v0, v1);
                    } else if (r == DD) {
                        g_bg[col]     = v0 + bias[col];
                        g_bg[col + 1] = v1 + bias[col + 1];
                    }
                    continue;
                }
                if (MODE == 3) {
                    v0 += bias[col]; v1 += bias[col + 1];
                } else if (MODE == 2) {
                    int bi = r >> 11;  // Nn = 2048
                    float gp0 = g_gp[(size_t)r * HH + col];
                    float gp1 = g_gp[(size_t)r * HH + col + 1];
                    float gg0 = 1.f / (1.f + expf(-(v0 + g_cvec[bi * HH + col])));
                    float gg1 = 1.f / (1.f + expf(-(v1 + g_cvec[bi * HH + col + 1])));
                    v0 = gg0 * gp0 + (1.f - gg0) * g_att[bi * HH + col];
                    v1 = gg1 * gp1 + (1.f - gg1) * g_att[bi * HH + col + 1];
                }
                *(float2*)&C[(size_t)r * NCOLS + col] = make_float2(v0, v1);
            }
        }
    }
}

// ---------------- launcher (single stream, 7 nodes) ----------------
extern "C" void kernel_launch(void* const* d_in, const int* in_sizes, int n_in,
                              void* d_out, int out_size) {
    const float* x      = (const float*)d_in[0];
    const float* text   = (const float*)d_in[1];
    const float* W      = (const float*)d_in[2];
    const float* bvec   = (const float*)d_in[3];
    const float* gate_w = (const float*)d_in[4];
    const float* gate_b = (const float*)d_in[5];
    const float* gnn_w  = (const float*)d_in[6];
    const float* gnn_b  = (const float*)d_in[7];
    const float* text_w = (const float*)d_in[8];
    const float* text_b = (const float*)d_in[9];
    const float* in_w   = (const float*)d_in[10];
    const float* in_b   = (const float*)d_in[11];
    const float* aow    = (const float*)d_in[12];
    const float* aob    = (const float*)d_in[13];
    const float* fgw    = (const float*)d_in[14];
    const float* fgb    = (const float*)d_in[15];
    const float* outp_w = (const float*)d_in[16];
    const float* outp_b = (const float*)d_in[17];
    const int*   en     = (const int*)d_in[18];
    float* outp = (float*)d_out;

    static bool once = false;
    if (!once) {
        cudaFuncSetAttribute(tgemm<0>, cudaFuncAttributeMaxDynamicSharedMemorySize, SMEM_BYTES);
        cudaFuncSetAttribute(tgemm<1>, cudaFuncAttributeMaxDynamicSharedMemorySize, SMEM_BYTES);
        cudaFuncSetAttribute(tgemm<2>, cudaFuncAttributeMaxDynamicSharedMemorySize, SMEM_BYTES);
        cudaFuncSetAttribute(tgemm<3>, cudaFuncAttributeMaxDynamicSharedMemorySize, SMEM_BYTES);
        once = true;
    }

    // Wg = [W;b] @ gnn_w (blocks 0..3) + k_init (blocks 4..259)
    tgemm<0><<<260, 256, SMEM_BYTES>>>(W, gnn_w, nullptr, gnn_b, bvec, x, gate_w);

    // edge build (+ alpha finalize in block 0)
    k_edge_a<<<EE * DEG / 256, 256>>>(en, gate_b);

    // y = x @ Wg  (tensor)
    tgemm<1><<<dim3(2, 64), 256, SMEM_BYTES>>>(x, nullptr, nullptr, nullptr, nullptr,
                                               nullptr, nullptr);

    // Medge + sort + per-batch constants (fused)
    k_edge_bsc<<<1092, 128>>>(en, text, text_w, text_b, in_w, in_b, aow, aob, fgw, fgb);

    // gp = alpha*y + (1-alpha)*L*y + bg
    k_gather<<<NN / 8, 256>>>();

    // fused = sigmoid(gp @ fgate_w0 + c[b]) * gp + (1-g) * att[b]
    tgemm<2><<<dim3(2, 64), 256, SMEM_BYTES>>>(nullptr, fgw, nullptr, nullptr, nullptr,
                                               nullptr, nullptr);

    // result = fused @ outp_w + outp_b
    tgemm<3><<<dim3(4, 64), 256, SMEM_BYTES>>>(nullptr, outp_w, outp, outp_b, nullptr,
                                               nullptr, nullptr);
}

// round 16
// speedup vs baseline: 1.5146x; 1.0319x over previous
#include <cuda_runtime.h>
#include <cuda_bf16.h>
#include <math.h>
#include <stdint.h>

#define NN   8192
#define DD   200
#define BB   4
#define EE   4096
#define DEG  16
#define HH   128
#define EPSf 1e-8f
#define MAXDEG 64

// ---------------- scratch ----------------
__device__ float g_y[NN * HH];
__device__ float g_Medge[EE * HH];
__device__ float g_gp[NN * HH];
__device__ float g_fused[NN * HH];
__device__ float g_Wg[DD * HH];
__device__ float g_bg[HH];
__device__ int   g_dv_cnt[NN];
__device__ int   g_de_cnt[EE];
__device__ unsigned g_maskbits[EE];
__device__ int   g_node_edges[NN * MAXDEG];
__device__ float g_alpha_part[256];
__device__ float g_alpha;
__device__ float g_att[BB * HH];
__device__ float g_cvec[BB * HH];

// ---------------- edge pass: slot-parallel dedup + degree + list fill ----------------
__global__ void __launch_bounds__(256) k_edge_a(const int* __restrict__ en,
                                                const float* __restrict__ gb) {
    if (blockIdx.x == 0) {
        __shared__ float smf[256];
        int t = threadIdx.x;
        smf[t] = g_alpha_part[t]; __syncthreads();
        for (int o = 128; o > 0; o >>= 1) { if (t < o) smf[t] += smf[t + o]; __syncthreads(); }
        if (t == 0) g_alpha = 1.f / (1.f + expf(-(smf[0] / (float)NN + gb[0])));
    }
    const int gt   = blockIdx.x * 256 + threadIdx.x;
    const int lane = threadIdx.x & 31;
    const int half = lane >> 4;
    const int s    = lane & 15;
    const int e    = (gt >> 5) * 2 + half;
    const int nd   = en[e * DEG + s];
    bool first = true;
#pragma unroll
    for (int j = 0; j < 15; j++) {
        int v = __shfl_sync(0xFFFFFFFFu, nd, (half << 4) + j);
        if (j < s && v == nd) first = false;
    }
    unsigned bal = __ballot_sync(0xFFFFFFFFu, first);
    unsigned m = (bal >> (half * 16)) & 0xFFFFu;
    if (s == 0) { g_maskbits[e] = m; g_de_cnt[e] = __popc(m); }
    if (first) {
        int p = atomicAdd(&g_dv_cnt[nd], 1);
        if (p < MAXDEG) g_node_edges[nd * MAXDEG + p] = e;
    }
}

// ---------------- per-batch constants: 2-way K split, 256 threads ----------------
__device__ void const_chain(int b, int tid,
        const float* __restrict__ text,
        const float* __restrict__ text_w, const float* __restrict__ text_b,
        const float* __restrict__ in_w,   const float* __restrict__ in_b,
        const float* __restrict__ aow,    const float* __restrict__ aob,
        const float* __restrict__ fgw,    const float* __restrict__ fgb) {
    __shared__ float part[2][HH];
    __shared__ float tp[HH], vv[HH], at[HH];
    const int j = tid & 127;
    const int h = tid >> 7;      // K-half
    float s;
    // stage 1: tp = text[b] @ text_w + text_b (K = 200)
    s = 0.f;
    {
        int k0 = h * 100, k1 = k0 + 100;
#pragma unroll 8
        for (int k = k0; k < k1; k++) s += text[b * DD + k] * text_w[k * HH + j];
    }
    part[h][j] = s; __syncthreads();
    if (h == 0) tp[j] = part[0][j] + part[1][j] + text_b[j];
    __syncthreads();
    // stage 2: vv = tp @ in_w[:,2H:3H] + in_b[2H:] (K = 128)
    s = 0.f;
    {
        int k0 = h * 64, k1 = k0 + 64;
#pragma unroll 8
        for (int k = k0; k < k1; k++) s += tp[k] * in_w[k * 3 * HH + 2 * HH + j];
    }
    part[h][j] = s; __syncthreads();
    if (h == 0) vv[j] = part[0][j] + part[1][j] + in_b[2 * HH + j];
    __syncthreads();
    // stage 3: at = vv @ aow + aob
    s = 0.f;
    {
        int k0 = h * 64, k1 = k0 + 64;
#pragma unroll 8
        for (int k = k0; k < k1; k++) s += vv[k] * aow[k * HH + j];
    }
    part[h][j] = s; __syncthreads();
    if (h == 0) {
        float v = part[0][j] + part[1][j] + aob[j];
        at[j] = v;
        g_att[b * HH + j] = v;
    }
    __syncthreads();
    // stage 4: cvec = at @ fgw[H:2H] + fgb
    s = 0.f;
    {
        int k0 = h * 64, k1 = k0 + 64;
#pragma unroll 8
        for (int k = k0; k < k1; k++) s += at[k] * fgw[(HH + k) * HH + j];
    }
    part[h][j] = s; __syncthreads();
    if (h == 0) g_cvec[b * HH + j] = part[0][j] + part[1][j] + fgb[j];
}

// ---------------- edge_b + sort (fused, 256 thr) ----------------
// blocks 0..511: Medge (8 edges each) ; 512..543: sort 256 nodes each
__global__ void __launch_bounds__(256) k_edge_bs(const int* __restrict__ en) {
    const int tid = threadIdx.x;
    if (blockIdx.x >= 512) {
        int n = (blockIdx.x - 512) * 256 + tid;
        int len = g_dv_cnt[n]; if (len > MAXDEG) len = MAXDEG;
        int* a = &g_node_edges[n * MAXDEG];
        for (int i = 1; i < len; i++) {
            int key = a[i]; int j = i - 1;
            while (j >= 0 && a[j] > key) { a[j + 1] = a[j]; j--; }
            a[j + 1] = key;
        }
        return;
    }
    __shared__ int   sn[8][DEG];
    __shared__ float sw[8][DEG];
    const int sub = tid >> 5, lane = tid & 31;
    const int e0 = blockIdx.x * 8;
    if (tid < 128) {
        int ee = tid >> 4, s = tid & 15;
        int e = e0 + ee;
        int n = en[e * DEG + s];
        sn[ee][s] = n;
        sw[ee][s] = ((g_maskbits[e] >> s) & 1u)
                      ? rsqrtf((float)g_dv_cnt[n] * (1.f / DEG) + EPSf) : 0.f;
    }
    __syncthreads();
    const int e = e0 + sub;
    float4 acc = make_float4(0.f, 0.f, 0.f, 0.f);
#pragma unroll
    for (int s = 0; s < DEG; s++) {
        float w = sw[sub][s];
        float4 v = ((const float4*)&g_y[(size_t)sn[sub][s] * HH])[lane];
        acc.x += w * v.x; acc.y += w * v.y; acc.z += w * v.z; acc.w += w * v.w;
    }
    float sc = 1.f / ((float)g_de_cnt[e] * (1.f / DEG) + EPSf) * (1.f / (DEG * DEG));
    ((float4*)&g_Medge[(size_t)e * HH])[lane] =
        make_float4(acc.x * sc, acc.y * sc, acc.z * sc, acc.w * sc);
}

// gp = alpha*y + (1-alpha)*dv*sum Medge + bg ; 8 nodes/block (warp per node)
__global__ void __launch_bounds__(256) k_gather() {
    const int n = blockIdx.x * 8 + (threadIdx.x >> 5);
    const int lane = threadIdx.x & 31;
    int len  = g_dv_cnt[n]; if (len > MAXDEG) len = MAXDEG;
    const int base = n * MAXDEG;
    const float dvn = rsqrtf((float)g_dv_cnt[n] * (1.f / DEG) + EPSf);
    const float alpha = g_alpha, beta = 1.f - alpha;
    float4 acc = make_float4(0.f, 0.f, 0.f, 0.f);
    for (int i = 0; i < len; i++) {
        int e = g_node_edges[base + i];
        float4 v = ((const float4*)&g_Medge[(size_t)e * HH])[lane];
        acc.x += v.x; acc.y += v.y; acc.z += v.z; acc.w += v.w;
    }
    float4 yv = ((const float4*)&g_y[(size_t)n * HH])[lane];
    float4 bg = ((const float4*)g_bg)[lane];
    ((float4*)&g_gp[(size_t)n * HH])[lane] =
        make_float4(alpha * yv.x + beta * dvn * acc.x + bg.x,
                    alpha * yv.y + beta * dvn * acc.y + bg.y,
                    alpha * yv.z + beta * dvn * acc.z + bg.z,
                    alpha * yv.w + beta * dvn * acc.w + bg.w);
}

// ---------------- tensor-core GEMM ----------------
// MODE 0: blocks 0..3 Wg GEMM ; 4..259 k_init body
// MODE 1: blocks 0..127 y = x@Wg ; 128..131 const chain
// MODE 2: gate epi ; MODE 3: output proj
__device__ __forceinline__ void mma_bf16(float* c, uint32_t a0, uint32_t a1,
                                         uint32_t a2, uint32_t a3,
                                         uint32_t b0, uint32_t b1) {
    asm volatile("mma.sync.aligned.m16n8k16.row.col.f32.bf16.bf16.f32 "
        "{%0,%1,%2,%3}, {%4,%5,%6,%7}, {%8,%9}, {%0,%1,%2,%3};"
        : "+f"(c[0]), "+f"(c[1]), "+f"(c[2]), "+f"(c[3])
        : "r"(a0), "r"(a1), "r"(a2), "r"(a3), "r"(b0), "r"(b1));
}
__device__ __forceinline__ void split2(float v0, float v1, uint32_t& hi, uint32_t& lo) {
    __nv_bfloat16 h0 = __float2bfloat16(v0), h1 = __float2bfloat16(v1);
    float l0 = v0 - __bfloat162float(h0);
    float l1 = v1 - __bfloat162float(h1);
    hi = (uint32_t)__bfloat16_as_ushort(h0) | ((uint32_t)__bfloat16_as_ushort(h1) << 16);
    lo = (uint32_t)__bfloat16_as_ushort(__float2bfloat16(l0))
       | ((uint32_t)__bfloat16_as_ushort(__float2bfloat16(l1)) << 16);
}

#define PST 40
#define STG2 (192 * PST)
#define SMEM_BYTES (2 * STG2 * 4)

template <int MODE>
__global__ void __launch_bounds__(256)
tgemm(const float* __restrict__ Aext, const float* __restrict__ Bext,
      float* __restrict__ Cext, const float* __restrict__ bias,
      const float* __restrict__ aux,
      const float* __restrict__ p0, const float* __restrict__ p1,
      const float* __restrict__ p2, const float* __restrict__ p3,
      const float* __restrict__ p4, const float* __restrict__ p5,
      const float* __restrict__ p6, const float* __restrict__ p7,
      const float* __restrict__ p8, const float* __restrict__ p9) {
    constexpr int NCOLS = (MODE == 3) ? 200 : 128;
    constexpr int K     = (MODE <= 1) ? 200 : 128;
    constexpr int LDA   = (MODE <= 1) ? 200 : 128;
    constexpr int NCH   = (K + 31) / 32;

    extern __shared__ uint32_t sm[];

    if (MODE == 0 && blockIdx.x >= 4) {
        // ===== k_init body: zero dv_cnt + alpha partial sums (p0 = x, p1 = gate_w) =====
        float* smf = (float*)sm;
        int t = threadIdx.x;
        int bb = blockIdx.x - 4;
        int gi = bb * 256 + t;
        if (gi < NN) g_dv_cnt[gi] = 0;
        float s = 0.f;
        for (int i = gi; i < NN * DD; i += 256 * 256)
            s += p0[i] * p1[i % DD];
        smf[t] = s; __syncthreads();
        for (int o = 128; o > 0; o >>= 1) { if (t < o) smf[t] += smf[t + o]; __syncthreads(); }
        if (t == 0) g_alpha_part[bb] = smf[0];
        return;
    }
    if (MODE == 1 && blockIdx.x >= 128) {
        // ===== per-batch const chain (p0..p9 = text,text_w,text_b,in_w,in_b,aow,aob,fgw,fgb) =====
        const_chain(blockIdx.x - 128, threadIdx.x,
                    p0, p1, p2, p3, p4, p5, p6, p7, p8);
        return;
    }

    const float* A = (MODE <= 1) ? Aext
                   : (MODE == 2) ? (const float*)g_gp : (const float*)g_fused;
    const float* Bsrc = (MODE == 1) ? (const float*)g_Wg : Bext;
    float* C = (MODE == 0) ? (float*)g_Wg
             : (MODE == 1) ? (float*)g_y
             : (MODE == 2) ? (float*)g_fused : Cext;

    const int tid = threadIdx.x;
    const int lane = tid & 31;
    const int w = tid >> 5;
    const int wm = w & 3, wn = w >> 2;
    const int g = lane >> 2, tig = lane & 3;
    const int m0 = (MODE <= 1) ? (int)(blockIdx.x >> 1) * 128 : blockIdx.y * 128;
    const int n0 = (MODE <= 1) ? (int)(blockIdx.x & 1) * 64  : blockIdx.x * 64;

    const int a_row = tid >> 3, a_kq = (tid & 7) * 4;
    const int b_m = tid & 15, b_nq = (tid >> 4) * 4;

    float acc[2][4][4];
#pragma unroll
    for (int mt = 0; mt < 2; mt++)
#pragma unroll
        for (int nt = 0; nt < 4; nt++)
#pragma unroll
            for (int j = 0; j < 4; j++) acc[mt][nt][j] = 0.f;

    const float4 z4 = make_float4(0.f, 0.f, 0.f, 0.f);
    float4 ar[4];
    float4 br0, br1;

    auto load_raw = [&](int k0) {
#pragma unroll
        for (int i = 0; i < 4; i++) {
            int row = a_row + i * 32;
            int gk = k0 + a_kq;
            if (gk >= K) { ar[i] = z4; continue; }
            if (MODE == 0) {
                int r = m0 + row;
                if (r < DD)       ar[i] = *(const float4*)&A[(size_t)r * DD + gk];
                else if (r == DD) ar[i] = *(const float4*)&aux[gk];
                else              ar[i] = z4;
            } else {
                ar[i] = *(const float4*)&A[(size_t)(m0 + row) * LDA + gk];
            }
        }
        int gk0 = k0 + 2 * b_m, gk1 = gk0 + 1, gn = n0 + b_nq;
        br0 = (gk0 < K && gn < NCOLS) ? *(const float4*)&Bsrc[(size_t)gk0 * NCOLS + gn] : z4;
        br1 = (gk1 < K && gn < NCOLS) ? *(const float4*)&Bsrc[(size_t)gk1 * NCOLS + gn] : z4;
    };
    auto store_smem = [&](int buf) {
        uint32_t* Ap = sm + buf * STG2;
        uint32_t* Bp = Ap + 128 * PST;
#pragma unroll
        for (int i = 0; i < 4; i++) {
            int row = a_row + i * 32;
            uint32_t h0, l0, h1, l1;
            split2(ar[i].x, ar[i].y, h0, l0);
            split2(ar[i].z, ar[i].w, h1, l1);
            uint32_t* p = Ap + row * PST + a_kq;
            p[0] = h0; p[1] = l0; p[2] = h1; p[3] = l1;
        }
        float b0e[4] = {br0.x, br0.y, br0.z, br0.w};
        float b1e[4] = {br1.x, br1.y, br1.z, br1.w};
#pragma unroll
        for (int q = 0; q < 4; q++) {
            uint32_t hi, lo;
            split2(b0e[q], b1e[q], hi, lo);
            uint32_t* p = Bp + (b_nq + q) * PST + 2 * b_m;
            p[0] = hi; p[1] = lo;
        }
    };

    load_raw(0);
    store_smem(0);
    __syncthreads();

    for (int ch = 0; ch < NCH; ch++) {
        const int buf = ch & 1;
        const uint32_t* Ap = sm + buf * STG2;
        const uint32_t* Bp = Ap + 128 * PST;
        if (ch + 1 < NCH) load_raw((ch + 1) * 32);
#pragma unroll
        for (int ks = 0; ks < 32; ks += 16) {
            uint32_t ah[2][4], al[2][4];
#pragma unroll
            for (int mt = 0; mt < 2; mt++) {
                int r = wm * 32 + mt * 16 + g;
                uint2 q0 = *(const uint2*)(Ap + r * PST + ks + tig * 2);
                uint2 q1 = *(const uint2*)(Ap + (r + 8) * PST + ks + tig * 2);
                uint2 q2 = *(const uint2*)(Ap + r * PST + ks + tig * 2 + 8);
                uint2 q3 = *(const uint2*)(Ap + (r + 8) * PST + ks + tig * 2 + 8);
                ah[mt][0] = q0.x; al[mt][0] = q0.y;
                ah[mt][1] = q1.x; al[mt][1] = q1.y;
                ah[mt][2] = q2.x; al[mt][2] = q2.y;
                ah[mt][3] = q3.x; al[mt][3] = q3.y;
            }
            uint32_t bh[4][2], bl[4][2];
#pragma unroll
            for (int nt = 0; nt < 4; nt++) {
                int n = wn * 32 + nt * 8 + g;
                uint2 q0 = *(const uint2*)(Bp + n * PST + ks + tig * 2);
                uint2 q1 = *(const uint2*)(Bp + n * PST + ks + tig * 2 + 8);
                bh[nt][0] = q0.x; bl[nt][0] = q0.y;
                bh[nt][1] = q1.x; bl[nt][1] = q1.y;
            }
#pragma unroll
            for (int mt = 0; mt < 2; mt++)
#pragma unroll
                for (int nt = 0; nt < 4; nt++) {
                    mma_bf16(acc[mt][nt], ah[mt][0], ah[mt][1], ah[mt][2], ah[mt][3],
                             bh[nt][0], bh[nt][1]);
                    mma_bf16(acc[mt][nt], al[mt][0], al[mt][1], al[mt][2], al[mt][3],
                             bh[nt][0], bh[nt][1]);
                    mma_bf16(acc[mt][nt], ah[mt][0], ah[mt][1], ah[mt][2], ah[mt][3],
                             bl[nt][0], bl[nt][1]);
                }
        }
        if (ch + 1 < NCH) store_smem(buf ^ 1);
        __syncthreads();
    }

    // ---- epilogue ----
#pragma unroll
    for (int mt = 0; mt < 2; mt++) {
#pragma unroll
        for (int nt = 0; nt < 4; nt++) {
            int row = m0 + wm * 32 + mt * 16 + g;
            int col = n0 + wn * 32 + nt * 8 + tig * 2;
            if (col >= NCOLS) continue;
            float* cc = acc[mt][nt];
#pragma unroll
            for (int h = 0; h < 2; h++) {
                int r = row + h * 8;
                float v0 = cc[h * 2], v1 = cc[h * 2 + 1];
                if (MODE == 0) {
                    if (r < DD) {
                        *(float2*)&C[(size_t)r * HH + col] = make_float2(v0, v1);
                    } else if (r == DD) {
                        g_bg[col]     = v0 + bias[col];
                        g_bg[col + 1] = v1 + bias[col + 1];
                    }
                    continue;
                }
                if (MODE == 3) {
                    v0 += bias[col]; v1 += bias[col + 1];
                } else if (MODE == 2) {
                    int bi = r >> 11;
                    float gp0 = g_gp[(size_t)r * HH + col];
                    float gp1 = g_gp[(size_t)r * HH + col + 1];
                    float gg0 = 1.f / (1.f + expf(-(v0 + g_cvec[bi * HH + col])));
                    float gg1 = 1.f / (1.f + expf(-(v1 + g_cvec[bi * HH + col + 1])));
                    v0 = gg0 * gp0 + (1.f - gg0) * g_att[bi * HH + col];
                    v1 = gg1 * gp1 + (1.f - gg1) * g_att[bi * HH + col + 1];
                }
                *(float2*)&C[(size_t)r * NCOLS + col] = make_float2(v0, v1);
            }
        }
    }
}

// ---------------- launcher (single stream, 6 nodes) ----------------
extern "C" void kernel_launch(void* const* d_in, const int* in_sizes, int n_in,
                              void* d_out, int out_size) {
    const float* x      = (const float*)d_in[0];
    const float* text   = (const float*)d_in[1];
    const float* W      = (const float*)d_in[2];
    const float* bvec   = (const float*)d_in[3];
    const float* gate_w = (const float*)d_in[4];
    const float* gate_b = (const float*)d_in[5];
    const float* gnn_w  = (const float*)d_in[6];
    const float* gnn_b  = (const float*)d_in[7];
    const float* text_w = (const float*)d_in[8];
    const float* text_b = (const float*)d_in[9];
    const float* in_w   = (const float*)d_in[10];
    const float* in_b   = (const float*)d_in[11];
    const float* aow    = (const float*)d_in[12];
    const float* aob    = (const float*)d_in[13];
    const float* fgw    = (const float*)d_in[14];
    const float* fgb    = (const float*)d_in[15];
    const float* outp_w = (const float*)d_in[16];
    const float* outp_b = (const float*)d_in[17];
    const int*   en     = (const int*)d_in[18];
    float* outp = (float*)d_out;

    static bool once = false;
    if (!once) {
        cudaFuncSetAttribute(tgemm<0>, cudaFuncAttributeMaxDynamicSharedMemorySize, SMEM_BYTES);
        cudaFuncSetAttribute(tgemm<1>, cudaFuncAttributeMaxDynamicSharedMemorySize, SMEM_BYTES);
        cudaFuncSetAttribute(tgemm<2>, cudaFuncAttributeMaxDynamicSharedMemorySize, SMEM_BYTES);
        cudaFuncSetAttribute(tgemm<3>, cudaFuncAttributeMaxDynamicSharedMemorySize, SMEM_BYTES);
        once = true;
    }

    // Wg = [W;b] @ gnn_w (blocks 0..3) + k_init (blocks 4..259)
    tgemm<0><<<260, 256, SMEM_BYTES>>>(W, gnn_w, nullptr, gnn_b, bvec,
                                       x, gate_w, nullptr, nullptr, nullptr,
                                       nullptr, nullptr, nullptr, nullptr, nullptr);

    // edge build (+ alpha finalize in block 0)
    k_edge_a<<<EE * DEG / 256, 256>>>(en, gate_b);

    // y = x @ Wg (blocks 0..127) + per-batch const chain (blocks 128..131)
    tgemm<1><<<132, 256, SMEM_BYTES>>>(x, nullptr, nullptr, nullptr, nullptr,
                                       text, text_w, text_b, in_w, in_b,
                                       aow, aob, fgw, fgb, nullptr);

    // Medge (512 blocks) + sort (32 blocks)
    k_edge_bs<<<544, 256>>>(en);

    // gp = alpha*y + (1-alpha)*L*y + bg
    k_gather<<<NN / 8, 256>>>();

    // fused = sigmoid(gp @ fgate_w0 + c[b]) * gp + (1-g) * att[b]
    tgemm<2><<<dim3(2, 64), 256, SMEM_BYTES>>>(nullptr, fgw, nullptr, nullptr, nullptr,
                                               nullptr, nullptr, nullptr, nullptr, nullptr,
                                               nullptr, nullptr, nullptr, nullptr, nullptr);

    // result = fused @ outp_w + outp_b
    tgemm<3><<<dim3(4, 64), 256, SMEM_BYTES>>>(nullptr, outp_w, outp, outp_b, nullptr,
                                               nullptr, nullptr, nullptr, nullptr, nullptr,
                                               nullptr, nullptr, nullptr, nullptr, nullptr);
}